// round 14
// baseline (speedup 1.0000x reference)
#include <cuda_runtime.h>

#define BATCH   128
#define NANCH   8732
#define NCLS    21
#define NLOG    25
#define MAXOUT  5
#define CONF    0.5f
#define DEC_T   128
#define NMS_T   256
#define CSTRIDE 32
#define SCAP    448
#define RCAP    2048
#define TILE_B  (DEC_T * NLOG * 4)         // 12800 bytes per tile

typedef unsigned int       u32;
typedef unsigned long long u64;

__device__ int    g_cnt[BATCH * CSTRIDE];
__device__ float4 g_cbox[BATCH * NANCH];
__device__ u64    g_ckey[BATCH * NANCH];
__device__ float  g_ccls[BATCH * NANCH];

__device__ __forceinline__ u32 smem_u32(const void* p) {
    u32 a;
    asm("{ .reg .u64 t; cvta.to.shared.u64 t, %1; cvt.u32.u64 %0, t; }"
        : "=r"(a) : "l"(p));
    return a;
}
__device__ __forceinline__ void mbar_init(u32 mbar, u32 cnt) {
    asm volatile("mbarrier.init.shared.b64 [%0], %1;" :: "r"(mbar), "r"(cnt)
                 : "memory");
}
__device__ __forceinline__ void mbar_expect_tx(u32 mbar, u32 bytes) {
    asm volatile("mbarrier.arrive.expect_tx.shared.b64 _, [%0], %1;"
                 :: "r"(mbar), "r"(bytes) : "memory");
}
__device__ __forceinline__ void bulk_ld(u32 dst, const void* src, u32 bytes,
                                        u32 mbar) {
    asm volatile(
        "cp.async.bulk.shared::cluster.global.mbarrier::complete_tx::bytes "
        "[%0], [%1], %2, [%3];"
        :: "r"(dst), "l"(src), "r"(bytes), "r"(mbar) : "memory");
}
__device__ __forceinline__ void mbar_wait(u32 mbar, u32 parity) {
    asm volatile(
        "{\n\t"
        ".reg .pred P;\n\t"
        "WL_%=:\n\t"
        "mbarrier.try_wait.parity.acquire.cta.shared::cta.b64 P, [%0], %1, 0x989680;\n\t"
        "@P bra.uni WD_%=;\n\t"
        "bra.uni WL_%=;\n\t"
        "WD_%=:\n\t"
        "}"
        :: "r"(mbar), "r"(parity) : "memory");
}

// ---------------------------------------------------------------------------
// Decode via TMA bulk: one thread issues 2 x 12.8KB cp.async.bulk at block
// start (both tiles in flight immediately, zero warp-path cost); threads then
// consume tile 0, tile 1. Per anchor: lazy argmax + softmax + compaction.
// ---------------------------------------------------------------------------
__global__ void __launch_bounds__(DEC_T)
decode_kernel(const float* __restrict__ logits, const float* __restrict__ db) {
    __shared__ __align__(16) float buf[2][DEC_T * NLOG];   // 2 x 12.8 KB
    __shared__ __align__(8)  u64   mbar[2];

    int tid = threadIdx.x;
    long long t0 = (long long)blockIdx.x * 2;              // first tile id

    u32 mb0 = smem_u32(&mbar[0]);
    u32 mb1 = smem_u32(&mbar[1]);

    if (tid == 0) {
        mbar_init(mb0, 1);
        mbar_init(mb1, 1);
    }
    __syncthreads();
    if (tid == 0) {
        const char* src = (const char*)logits + (size_t)t0 * TILE_B;
        mbar_expect_tx(mb0, TILE_B);
        bulk_ld(smem_u32(buf[0]), src, TILE_B, mb0);
        mbar_expect_tx(mb1, TILE_B);
        bulk_ld(smem_u32(buf[1]), src + TILE_B, TILE_B, mb1);
    }

#pragma unroll
    for (int s = 0; s < 2; s++) {
        mbar_wait(s == 0 ? mb0 : mb1, 0);

        const float* L = buf[s] + tid * NLOG;
        int gid = (int)((t0 + s) * DEC_T) + tid;

        float c0 = L[4];                   // background logit
        float m1 = L[5];                   // max over classes 1..20
#pragma unroll
        for (int c = 2; c < NCLS; c++) m1 = fmaxf(m1, L[4 + c]);
        float mx = fmaxf(c0, m1);

        float sum = 0.f;
#pragma unroll
        for (int c = 0; c < NCLS; c++) sum += __expf(L[4 + c] - mx);
        float score = 1.0f / sum;

        if (m1 > c0 && score > CONF) {     // argmax != 0 && score > 0.5
            int bi = 1;                    // first-occurrence class 1..20
#pragma unroll
            for (int c = NCLS - 1; c >= 1; c--) if (L[4 + c] == m1) bi = c;

            int b = gid / NANCH;
            int n = gid % NANCH;
            float4 d = ((const float4*)db)[n];             // y0,x0,y1,x1
            float cy = 0.5f * (d.z + d.x);
            float cx = 0.5f * (d.w + d.y);
            float h  = d.z - d.x;
            float w  = d.w - d.y;
            float ncy = L[0] * h + cy;
            float ncx = L[1] * w + cx;
            float nh  = __expf(L[2]) * h;
            float nw  = __expf(L[3]) * w;
            float4 box;
            box.x = fminf(fmaxf(ncy - 0.5f * nh, 0.f), 1.f);
            box.y = fminf(fmaxf(ncx - 0.5f * nw, 0.f), 1.f);
            box.z = fminf(fmaxf(ncy + 0.5f * nh, 0.f), 1.f);
            box.w = fminf(fmaxf(ncx + 0.5f * nw, 0.f), 1.f);

            int slot = atomicAdd(&g_cnt[b * CSTRIDE], 1);
            size_t o = (size_t)b * NANCH + slot;
            u32 hi = __float_as_uint(score) | 0x80000000u;
            u32 lo = ((u32)(NANCH - n) << 14) | (u32)slot;
            g_ckey[o] = ((u64)hi << 32) | lo;
            g_cbox[o] = box;
            g_ccls[o] = (float)bi;
        }
    }
    cudaTriggerProgrammaticLaunchCompletion();
}

// ---------------------------------------------------------------------------
// NMS (R11-proven): stage to smem, warp 0 runs no-store bitmask suppress+argmax.
// ---------------------------------------------------------------------------
__global__ void __launch_bounds__(NMS_T)
nms_kernel(float* __restrict__ out) {
    __shared__ u64    skey[SCAP];
    __shared__ float4 sbox[SCAP];

    cudaGridDependencySynchronize();

    int b   = blockIdx.x;
    int tid = threadIdx.x;
    int M   = g_cnt[b * CSTRIDE];
    size_t base = (size_t)b * NANCH;

    bool fits = (M <= SCAP);
    if (fits) {
        for (int i = tid; i < M; i += NMS_T) {
            skey[i] = g_ckey[base + i];
            sbox[i] = g_cbox[base + i];
        }
    }
    __syncthreads();
    if (tid == 0) g_cnt[b * CSTRIDE] = 0;

    if (tid >= 32) return;
    float* ob = out + (size_t)b * MAXOUT * 6;

    if (M <= RCAP) {
        const u64*    __restrict__ keys  = fits ? skey : (g_ckey + base);
        const float4* __restrict__ boxes = fits ? sbox : (g_cbox + base);
        u64 alive = ~0ull;
        u64 bp = 0ull;
        for (int i = tid; i < M; i += 32) {
            u64 k = keys[i];
            if (k > bp) bp = k;
        }
#pragma unroll
        for (int off = 16; off > 0; off >>= 1) {
            u64 o = __shfl_xor_sync(0xffffffffu, bp, off);
            if (o > bp) bp = o;
        }
        for (int t = 0; t < MAXOUT; t++) {
            if (bp == 0ull) {
                if (tid == 0)
                    for (int tt = t; tt < MAXOUT; tt++) {
                        float* o = ob + tt * 6;
                        o[0]=o[1]=o[2]=o[3]=o[4]=o[5]=0.f;
                    }
                return;
            }
            int   pos = (int)(bp & 0x3FFFull);
            float sc  = __uint_as_float((u32)(bp >> 32) & 0x7FFFFFFFu);
            float4 B  = boxes[pos];
            if (tid == 0) {
                float* o = ob + t * 6;
                o[0]=B.x; o[1]=B.y; o[2]=B.z; o[3]=B.w;
                o[4]=g_ccls[base + pos]; o[5]=sc;
            }
            if (t == MAXOUT - 1) return;

            float a1 = (B.z - B.x) * (B.w - B.y);
            bp = 0ull;
            int kk = 0;
            for (int i = tid; i < M; i += 32, kk++) {
                if (!((alive >> kk) & 1ull)) continue;
                float4 C = boxes[i];
                float ty  = fmaxf(B.x, C.x);
                float tx  = fmaxf(B.y, C.y);
                float by  = fminf(B.z, C.z);
                float bxr = fminf(B.w, C.w);
                float hh  = fmaxf(by - ty, 0.f);
                float ww  = fmaxf(bxr - tx, 0.f);
                float inter = hh * ww;
                float a2 = (C.z - C.x) * (C.w - C.y);
                float iou = inter / (a1 + a2 - inter + 1e-12f);
                if (iou > 0.5f) alive &= ~(1ull << kk);
                else {
                    u64 k = keys[i];
                    if (k > bp) bp = k;
                }
            }
#pragma unroll
            for (int off = 16; off > 0; off >>= 1) {
                u64 o = __shfl_xor_sync(0xffffffffu, bp, off);
                if (o > bp) bp = o;
            }
        }
    } else {
        // destructive fallback (never expected at these sizes)
        u64* kg = g_ckey + base;
        const float4* boxes = g_cbox + base;
        u64 bp = 0ull;
        for (int i = tid; i < M; i += 32) {
            u64 k = kg[i];
            if (k > bp) bp = k;
        }
#pragma unroll
        for (int off = 16; off > 0; off >>= 1) {
            u64 o = __shfl_xor_sync(0xffffffffu, bp, off);
            if (o > bp) bp = o;
        }
        for (int t = 0; t < MAXOUT; t++) {
            if (bp == 0ull) {
                if (tid == 0)
                    for (int tt = t; tt < MAXOUT; tt++) {
                        float* o = ob + tt * 6;
                        o[0]=o[1]=o[2]=o[3]=o[4]=o[5]=0.f;
                    }
                return;
            }
            int   pos = (int)(bp & 0x3FFFull);
            float sc  = __uint_as_float((u32)(bp >> 32) & 0x7FFFFFFFu);
            float4 B  = boxes[pos];
            if (tid == 0) {
                float* o = ob + t * 6;
                o[0]=B.x; o[1]=B.y; o[2]=B.z; o[3]=B.w;
                o[4]=g_ccls[base + pos]; o[5]=sc;
            }
            if (t == MAXOUT - 1) return;
            float a1 = (B.z - B.x) * (B.w - B.y);
            bp = 0ull;
            for (int i = tid; i < M; i += 32) {
                u64 k = kg[i];
                if (!k) continue;
                float4 C = boxes[i];
                float ty  = fmaxf(B.x, C.x);
                float tx  = fmaxf(B.y, C.y);
                float by  = fminf(B.z, C.z);
                float bxr = fminf(B.w, C.w);
                float hh  = fmaxf(by - ty, 0.f);
                float ww  = fmaxf(bxr - tx, 0.f);
                float inter = hh * ww;
                float a2 = (C.z - C.x) * (C.w - C.y);
                float iou = inter / (a1 + a2 - inter + 1e-12f);
                if (iou > 0.5f) kg[i] = 0ull;
                else if (k > bp) bp = k;
            }
#pragma unroll
            for (int off = 16; off > 0; off >>= 1) {
                u64 o = __shfl_xor_sync(0xffffffffu, bp, off);
                if (o > bp) bp = o;
            }
        }
    }
}

// ---------------------------------------------------------------------------
extern "C" void kernel_launch(void* const* d_in, const int* in_sizes, int n_in,
                              void* d_out, int out_size) {
    const float* logits = (const float*)d_in[0];   // [128, 8732, 25]
    const float* db     = (const float*)d_in[1];   // [8732, 4]
    float*       out    = (float*)d_out;           // [128, 5, 6]

    decode_kernel<<<BATCH * NANCH / (2 * DEC_T), DEC_T>>>(logits, db);

    cudaLaunchConfig_t cfg = {};
    cfg.gridDim  = dim3(BATCH);
    cfg.blockDim = dim3(NMS_T);
    cfg.dynamicSmemBytes = 0;
    cfg.stream = 0;
    cudaLaunchAttribute attr[1];
    attr[0].id = cudaLaunchAttributeProgrammaticStreamSerialization;
    attr[0].val.programmaticStreamSerializationAllowed = 1;
    cfg.attrs = attr;
    cfg.numAttrs = 1;
    cudaLaunchKernelEx(&cfg, nms_kernel, out);
}